// round 3
// baseline (speedup 1.0000x reference)
#include <cuda_runtime.h>

// out[to_i[j]] = mat_i[from_i[j]], 3 segments, D=64 fp32 per row (256B).
// One thread per float4 (16 threads per row). Pure HBM-bound streaming
// gather/scatter; rows are 256B-aligned so all accesses are sector-perfect.

#define D4 16  // D=64 floats = 16 float4

__global__ void __launch_bounds__(256)
multi_index_select_kernel(const float4* __restrict__ m0,
                          const float4* __restrict__ m1,
                          const float4* __restrict__ m2,
                          const int*    __restrict__ f0,
                          const int*    __restrict__ f1,
                          const int*    __restrict__ f2,
                          const int*    __restrict__ t0,
                          const int*    __restrict__ t1,
                          const int*    __restrict__ t2,
                          float4*       __restrict__ out,
                          int L)
{
    int tid = blockIdx.x * blockDim.x + threadIdx.x;   // < 3*L*16 < 2^31
    int row = tid >> 4;
    int q   = tid & (D4 - 1);
    if (row >= 3 * L) return;

    const float4* __restrict__ m;
    const int* __restrict__ f;
    const int* __restrict__ t;
    int r;
    if (row < L)           { m = m0; f = f0; t = t0; r = row;         }
    else if (row < 2 * L)  { m = m1; f = f1; t = t1; r = row - L;     }
    else                   { m = m2; f = f2; t = t2; r = row - 2 * L; }

    int src = __ldg(f + r);
    int dst = __ldg(t + r);
    out[dst * D4 + q] = __ldg(m + src * D4 + q);
}

extern "C" void kernel_launch(void* const* d_in, const int* in_sizes, int n_in,
                              void* d_out, int out_size)
{
    const float4* m0 = (const float4*)d_in[0];
    const float4* m1 = (const float4*)d_in[1];
    const float4* m2 = (const float4*)d_in[2];
    const int*    f0 = (const int*)d_in[3];
    const int*    f1 = (const int*)d_in[4];
    const int*    f2 = (const int*)d_in[5];
    const int*    t0 = (const int*)d_in[6];
    const int*    t1 = (const int*)d_in[7];
    const int*    t2 = (const int*)d_in[8];
    float4* out = (float4*)d_out;

    const int L = in_sizes[3];               // length of from0
    const long long threads = (long long)3 * L * D4;
    const int block = 256;
    const int grid = (int)((threads + block - 1) / block);

    multi_index_select_kernel<<<grid, block>>>(m0, m1, m2,
                                               f0, f1, f2,
                                               t0, t1, t2,
                                               out, L);
}

// round 4
// speedup vs baseline: 1.2673x; 1.2673x over previous
#include <cuda_runtime.h>

// out[to_i[j]] = mat_i[from_i[j]], 3 segments, D=64 fp32 per row (256B).
// 16 threads per row (one float4 each). Each thread processes U rows spaced
// by totalRows/U so intra-group coalescing is preserved, with software
// pipelining: all index loads -> all data loads -> all stores, giving
// per-thread MLP=U on the data phase instead of a serial idx->data->store
// chain with MLP=1.

#define D4 16   // D=64 floats = 16 float4
#define U  4    // rows per thread

__global__ void __launch_bounds__(256)
multi_index_select_kernel(const float4* __restrict__ m0,
                          const float4* __restrict__ m1,
                          const float4* __restrict__ m2,
                          const int*    __restrict__ f0,
                          const int*    __restrict__ f1,
                          const int*    __restrict__ f2,
                          const int*    __restrict__ t0,
                          const int*    __restrict__ t1,
                          const int*    __restrict__ t2,
                          float4*       __restrict__ out,
                          int L, int totalRows, int rowStride)
{
    const int tid  = blockIdx.x * blockDim.x + threadIdx.x;
    const int q    = tid & (D4 - 1);
    const int row0 = tid >> 4;

    const float4* srcp[U];
    float4*       dstp[U];
    bool          act[U];

    // Phase 1: resolve segments + issue all index loads (independent LDGs,
    // ptxas front-batches them after unroll).
    #pragma unroll
    for (int k = 0; k < U; k++) {
        const int row = row0 + k * rowStride;
        act[k] = (row < totalRows);
        const float4* m; const int* f; const int* t; int r;
        if (row < L)          { m = m0; f = f0; t = t0; r = row;         }
        else if (row < 2 * L) { m = m1; f = f1; t = t1; r = row - L;     }
        else                  { m = m2; f = f2; t = t2; r = row - 2 * L; }
        const int rr = act[k] ? r : 0;
        const int s  = __ldg(f + rr);
        const int d  = __ldg(t + rr);
        srcp[k] = m   + (size_t)s * D4 + q;
        dstp[k] = out + (size_t)d * D4 + q;
    }

    // Phase 2: U independent data loads in flight.
    float4 v[U];
    #pragma unroll
    for (int k = 0; k < U; k++) {
        if (act[k]) v[k] = __ldg(srcp[k]);
    }

    // Phase 3: stores.
    #pragma unroll
    for (int k = 0; k < U; k++) {
        if (act[k]) *dstp[k] = v[k];
    }
}

extern "C" void kernel_launch(void* const* d_in, const int* in_sizes, int n_in,
                              void* d_out, int out_size)
{
    const float4* m0 = (const float4*)d_in[0];
    const float4* m1 = (const float4*)d_in[1];
    const float4* m2 = (const float4*)d_in[2];
    const int*    f0 = (const int*)d_in[3];
    const int*    f1 = (const int*)d_in[4];
    const int*    f2 = (const int*)d_in[5];
    const int*    t0 = (const int*)d_in[6];
    const int*    t1 = (const int*)d_in[7];
    const int*    t2 = (const int*)d_in[8];
    float4* out = (float4*)d_out;

    const int L         = in_sizes[3];            // length of from0
    const int totalRows = 3 * L;
    const int rowStride = (totalRows + U - 1) / U;      // rows covered per k-step
    const long long threads = (long long)rowStride * D4;
    const int block = 256;
    const int grid  = (int)((threads + block - 1) / block);

    multi_index_select_kernel<<<grid, block>>>(m0, m1, m2,
                                               f0, f1, f2,
                                               t0, t1, t2,
                                               out, L, totalRows, rowStride);
}